// round 4
// baseline (speedup 1.0000x reference)
#include <cuda_runtime.h>

#define EPSV     1e-4f
#define EPSV2    1e-8f         // EPSV^2
#define TOLSQ    1e-8f         // (1e-4)^2 relative orthogonality threshold
#define MAXSWEEP 24

// One CTA per 64x64 SPD matrix. One-sided Jacobi (SVD of symmetric PSD == eig).
// M column-major in shared: M[col*64 + row].
// Hybrid norm tracking: sqn[] holds exact column squared-norms, refreshed by
// RECOMPUTING from the rotated register values at rotation time (cancellation-
// free). Only the shrinking column needs the butterfly; the growing one is
// (dpp+dqq) - small. Non-rotating visits cost only the dpq dot.
// ALL shfls that can execute under half-warp divergence use the half-warp
// mask (R3 post-mortem: full-mask shfl inside the divergent rotation branch
// deadlocked the warp).
__global__ void __launch_bounds__(256, 4)
logm_jacobi_kernel(const float* __restrict__ in, float* __restrict__ out)
{
    __shared__ __align__(16) float M[64 * 64];
    __shared__ float sqn[64];      // exact column squared-norms
    __shared__ float wlog[64];     // log(max(lambda, eps))
    __shared__ int   s_flag;

    const int tid  = threadIdx.x;
    const int lane = tid & 31;
    const int warp = tid >> 5;
    const int sub  = lane >> 4;    // which of 2 pairs this half-warp handles
    const int sl   = lane & 15;    // lane within the 16-lane half
    const unsigned hm = 0xffffu << (sub << 4);   // half-warp shfl mask
    const size_t base = (size_t)blockIdx.x * 4096;

    // ---- load X (symmetric, so flat row-major copy == column-major) ----
    {
        const float4* g4 = reinterpret_cast<const float4*>(in + base);
        float4* m4 = reinterpret_cast<float4*>(M);
        #pragma unroll
        for (int i = 0; i < 4; ++i) m4[tid + 256 * i] = g4[tid + 256 * i];
    }
    __syncthreads();

    // ---- initial exact column squared-norms ----
    for (int k = warp; k < 64; k += 8) {
        float2 v = *reinterpret_cast<float2*>(M + k * 64 + 2 * lane);
        float ss = v.x * v.x + v.y * v.y;
        #pragma unroll
        for (int o = 16; o; o >>= 1) ss += __shfl_xor_sync(0xffffffffu, ss, o);
        if (lane == 0) sqn[k] = ss;
    }
    __syncthreads();

    // ---- one-sided Jacobi sweeps ----
    for (int sweep = 0; sweep < MAXSWEEP; ++sweep) {
        if (tid == 0) s_flag = 0;
        __syncthreads();

        for (int r = 0; r < 63; ++r) {
            // 32 disjoint pairs per round (circle method); each warp handles 2
            // pairs simultaneously (16 lanes each, float4/lane), twice (h).
            #pragma unroll
            for (int h = 0; h < 2; ++h) {
                int k = h * 16 + warp * 2 + sub;
                int p, q;
                if (k == 0) { p = 63; q = r; }
                else {
                    p = r + k;      if (p >= 63) p -= 63;
                    q = r + 63 - k; if (q >= 63) q -= 63;
                }
                float4* cp4 = reinterpret_cast<float4*>(M + p * 64) + sl;
                float4* cq4 = reinterpret_cast<float4*>(M + q * 64) + sl;
                float4 ap = *cp4;
                float4 aq = *cq4;

                // single cross-dot; dpp/dqq come from tracked exact norms
                float dpq = ap.x * aq.x + ap.y * aq.y + ap.z * aq.z + ap.w * aq.w;
                #pragma unroll
                for (int o = 8; o; o >>= 1)
                    dpq += __shfl_xor_sync(hm, dpq, o);

                float dpp = sqn[p];
                float dqq = sqn[q];

                if (dpq * dpq > TOLSQ * dpp * dqq) {
                    float tau = __fdividef(dqq - dpp, 2.0f * dpq);
                    float t = copysignf(1.0f, tau) /
                              (fabsf(tau) + sqrtf(1.0f + tau * tau));
                    float c = rsqrtf(1.0f + t * t);
                    float s = t * c;
                    float4 np, nq;
                    np.x = c * ap.x - s * aq.x;  np.y = c * ap.y - s * aq.y;
                    np.z = c * ap.z - s * aq.z;  np.w = c * ap.w - s * aq.w;
                    nq.x = s * ap.x + c * aq.x;  nq.y = s * ap.y + c * aq.y;
                    nq.z = s * ap.z + c * aq.z;  nq.w = s * ap.w + c * aq.w;
                    *cp4 = np;
                    *cq4 = nq;

                    // recompute the SHRINKING column's norm exactly; derive
                    // the growing one from the invariant sum (no cancellation)
                    bool pshr = (dqq >= dpp);   // p shrinks iff q was larger
                    float4 v;
                    v.x = pshr ? np.x : nq.x;  v.y = pshr ? np.y : nq.y;
                    v.z = pshr ? np.z : nq.z;  v.w = pshr ? np.w : nq.w;
                    float small = v.x * v.x + v.y * v.y + v.z * v.z + v.w * v.w;
                    #pragma unroll
                    for (int o = 8; o; o >>= 1)
                        small += __shfl_xor_sync(hm, small, o);   // half-mask!

                    if (sl == 0) {
                        float big = (dpp + dqq) - small;
                        sqn[p] = pshr ? small : big;
                        sqn[q] = pshr ? big   : small;
                        s_flag = 1;
                    }
                }
            }
            __syncthreads();
        }

        int active = s_flag;
        __syncthreads();          // protect flag read vs next-sweep reset
        if (!active) break;
    }

    // ---- eigenvalues from tracked norms; normalize columns -> eigenvectors ----
    for (int k = warp; k < 64; k += 8) {
        float ss = sqn[k];
        float inv = (ss > 1e-30f) ? rsqrtf(ss) : 0.0f;
        float2 v = *reinterpret_cast<float2*>(M + k * 64 + 2 * lane);
        v.x *= inv; v.y *= inv;
        *reinterpret_cast<float2*>(M + k * 64 + 2 * lane) = v;
        if (lane == 0) wlog[k] = 0.5f * logf(fmaxf(ss, EPSV2));
    }
    __syncthreads();

    // ---- O = U diag(w) U^T, 4x4 register tile per thread ----
    const int ta = tid >> 4;      // tile row block (0..15)
    const int tb = tid & 15;      // tile col block (0..15)
    float acc[4][4];
    #pragma unroll
    for (int i = 0; i < 4; ++i)
        #pragma unroll
        for (int j = 0; j < 4; ++j) acc[i][j] = 0.0f;

    for (int k = 0; k < 64; ++k) {
        float w = wlog[k];
        float4 ur = *reinterpret_cast<const float4*>(M + k * 64 + 4 * ta);
        float4 uc = *reinterpret_cast<const float4*>(M + k * 64 + 4 * tb);
        float r0 = w * ur.x, r1 = w * ur.y, r2 = w * ur.z, r3 = w * ur.w;
        acc[0][0] += r0 * uc.x; acc[0][1] += r0 * uc.y; acc[0][2] += r0 * uc.z; acc[0][3] += r0 * uc.w;
        acc[1][0] += r1 * uc.x; acc[1][1] += r1 * uc.y; acc[1][2] += r1 * uc.z; acc[1][3] += r1 * uc.w;
        acc[2][0] += r2 * uc.x; acc[2][1] += r2 * uc.y; acc[2][2] += r2 * uc.z; acc[2][3] += r2 * uc.w;
        acc[3][0] += r3 * uc.x; acc[3][1] += r3 * uc.y; acc[3][2] += r3 * uc.z; acc[3][3] += r3 * uc.w;
    }

    float* go = out + base;
    #pragma unroll
    for (int i = 0; i < 4; ++i) {
        float4 v = make_float4(acc[i][0], acc[i][1], acc[i][2], acc[i][3]);
        *reinterpret_cast<float4*>(go + (4 * ta + i) * 64 + 4 * tb) = v;
    }
}

extern "C" void kernel_launch(void* const* d_in, const int* in_sizes, int n_in,
                              void* d_out, int out_size)
{
    const float* x = (const float*)d_in[0];
    float* out = (float*)d_out;
    int batches = in_sizes[0] / 4096;   // 64*64 elements per matrix
    logm_jacobi_kernel<<<batches, 256>>>(x, out);
}

// round 5
// speedup vs baseline: 1.0146x; 1.0146x over previous
#include <cuda_runtime.h>

#define EPSV     1e-4f
#define EPSV2    1e-8f
#define TOLSQ    1e-10f        // (1e-5)^2 relative orthogonality threshold
#define MAXSWEEP 24

typedef unsigned long long u64;

// ---- packed f32x2 helpers (sm_10x; ptxas never emits these from C++) ----
__device__ __forceinline__ u64 mul2(u64 a, u64 b) {
    u64 r; asm("mul.rn.f32x2 %0, %1, %2;" : "=l"(r) : "l"(a), "l"(b)); return r;
}
__device__ __forceinline__ u64 fma2(u64 a, u64 b, u64 c) {
    u64 r; asm("fma.rn.f32x2 %0, %1, %2, %3;" : "=l"(r) : "l"(a), "l"(b), "l"(c)); return r;
}
__device__ __forceinline__ u64 pack2(float lo, float hi) {
    u64 r; asm("mov.b64 %0, {%1, %2};" : "=l"(r) : "f"(lo), "f"(hi)); return r;
}
__device__ __forceinline__ float hadd2(u64 a) {
    float lo, hi; asm("mov.b64 {%0, %1}, %2;" : "=f"(lo), "=f"(hi) : "l"(a));
    return lo + hi;
}

// One CTA per 64x64 SPD matrix. One-sided Jacobi, M column-major in shared.
// 8-lane teams: each team owns one pair per round (8 floats = 4 u64 per lane),
// a warp retires 4 pairs per slot. All pair dots computed exactly (3 dots,
// independent chains for ILP). All shfls unconditional; branch body shfl-free.
__global__ void __launch_bounds__(256, 4)
logm_jacobi_kernel(const float* __restrict__ in, float* __restrict__ out)
{
    __shared__ __align__(16) float M[64 * 64];
    __shared__ float wlog[64];
    __shared__ int   s_flag;

    const int tid  = threadIdx.x;
    const int lane = tid & 31;
    const int warp = tid >> 5;
    const int team = lane >> 3;            // 4 teams of 8 lanes per warp
    const int sl   = lane & 7;             // lane within team
    const unsigned tm = 0xffu << (team << 3);  // team shfl mask
    const int kidx = warp * 4 + team;      // pair slot 0..31
    const size_t base = (size_t)blockIdx.x * 4096;

    // ---- load X (symmetric: flat copy == column-major) ----
    {
        const float4* g4 = reinterpret_cast<const float4*>(in + base);
        float4* m4 = reinterpret_cast<float4*>(M);
        #pragma unroll
        for (int i = 0; i < 4; ++i) m4[tid + 256 * i] = g4[tid + 256 * i];
    }
    __syncthreads();

    // ---- one-sided Jacobi sweeps ----
    for (int sweep = 0; sweep < MAXSWEEP; ++sweep) {
        if (tid == 0) s_flag = 0;
        __syncthreads();

        for (int r = 0; r < 63; ++r) {
            int p, q;
            if (kidx == 0) { p = 63; q = r; }
            else {
                p = r + kidx;      if (p >= 63) p -= 63;
                q = r + 63 - kidx; if (q >= 63) q -= 63;
            }
            // 8 floats per lane per column = 2x ulonglong2
            ulonglong2* cp = reinterpret_cast<ulonglong2*>(M + p * 64 + sl * 8);
            ulonglong2* cq = reinterpret_cast<ulonglong2*>(M + q * 64 + sl * 8);
            ulonglong2 a01 = cp[0], a23 = cp[1];
            ulonglong2 b01 = cq[0], b23 = cq[1];

            // three exact dots, independent packed chains
            u64 dpq2 = mul2(a01.x, b01.x);
            u64 dpp2 = mul2(a01.x, a01.x);
            u64 dqq2 = mul2(b01.x, b01.x);
            dpq2 = fma2(a01.y, b01.y, dpq2);
            dpp2 = fma2(a01.y, a01.y, dpp2);
            dqq2 = fma2(b01.y, b01.y, dqq2);
            dpq2 = fma2(a23.x, b23.x, dpq2);
            dpp2 = fma2(a23.x, a23.x, dpp2);
            dqq2 = fma2(b23.x, b23.x, dqq2);
            dpq2 = fma2(a23.y, b23.y, dpq2);
            dpp2 = fma2(a23.y, a23.y, dpp2);
            dqq2 = fma2(b23.y, b23.y, dqq2);

            float dpq = hadd2(dpq2);
            float dpp = hadd2(dpp2);
            float dqq = hadd2(dqq2);
            #pragma unroll
            for (int o = 4; o; o >>= 1) {           // unconditional shfls
                dpq += __shfl_xor_sync(tm, dpq, o);
                dpp += __shfl_xor_sync(tm, dpp, o);
                dqq += __shfl_xor_sync(tm, dqq, o);
            }

            if (dpq * dpq > TOLSQ * dpp * dqq) {    // shfl-free branch body
                float tau = __fdividef(dqq - dpp, 2.0f * dpq);
                float t = copysignf(1.0f, tau) /
                          (fabsf(tau) + sqrtf(1.0f + tau * tau));
                float c = rsqrtf(1.0f + t * t);
                float s = t * c;
                u64 c2  = pack2(c, c);
                u64 s2  = pack2(s, s);
                u64 ms2 = pack2(-s, -s);
                ulonglong2 np, nq;
                np.x = fma2(ms2, b01.x, mul2(c2, a01.x));
                np.y = fma2(ms2, b01.y, mul2(c2, a01.y));
                nq.x = fma2(s2,  a01.x, mul2(c2, b01.x));
                nq.y = fma2(s2,  a01.y, mul2(c2, b01.y));
                cp[0] = np;
                cq[0] = nq;
                np.x = fma2(ms2, b23.x, mul2(c2, a23.x));
                np.y = fma2(ms2, b23.y, mul2(c2, a23.y));
                nq.x = fma2(s2,  a23.x, mul2(c2, b23.x));
                nq.y = fma2(s2,  a23.y, mul2(c2, b23.y));
                cp[1] = np;
                cq[1] = nq;
                if (sl == 0) s_flag = 1;
            }
            __syncthreads();
        }

        int active = s_flag;
        __syncthreads();
        if (!active) break;
    }

    // ---- exact column norms -> eigenvalues; normalize -> eigenvectors ----
    for (int k = warp; k < 64; k += 8) {
        float2 v = *reinterpret_cast<float2*>(M + k * 64 + 2 * lane);
        float ss = v.x * v.x + v.y * v.y;
        #pragma unroll
        for (int o = 16; o; o >>= 1) ss += __shfl_xor_sync(0xffffffffu, ss, o);
        float nrm = sqrtf(ss);
        float inv = (nrm > 0.0f) ? (1.0f / nrm) : 0.0f;
        v.x *= inv; v.y *= inv;
        *reinterpret_cast<float2*>(M + k * 64 + 2 * lane) = v;
        if (lane == 0) wlog[k] = logf(fmaxf(nrm, EPSV));
    }
    __syncthreads();

    // ---- O = U diag(w) U^T, 4x4 register tile per thread ----
    const int ta = tid >> 4;
    const int tb = tid & 15;
    float acc[4][4];
    #pragma unroll
    for (int i = 0; i < 4; ++i)
        #pragma unroll
        for (int j = 0; j < 4; ++j) acc[i][j] = 0.0f;

    for (int k = 0; k < 64; ++k) {
        float w = wlog[k];
        float4 ur = *reinterpret_cast<const float4*>(M + k * 64 + 4 * ta);
        float4 uc = *reinterpret_cast<const float4*>(M + k * 64 + 4 * tb);
        float r0 = w * ur.x, r1 = w * ur.y, r2 = w * ur.z, r3 = w * ur.w;
        acc[0][0] += r0 * uc.x; acc[0][1] += r0 * uc.y; acc[0][2] += r0 * uc.z; acc[0][3] += r0 * uc.w;
        acc[1][0] += r1 * uc.x; acc[1][1] += r1 * uc.y; acc[1][2] += r1 * uc.z; acc[1][3] += r1 * uc.w;
        acc[2][0] += r2 * uc.x; acc[2][1] += r2 * uc.y; acc[2][2] += r2 * uc.z; acc[2][3] += r2 * uc.w;
        acc[3][0] += r3 * uc.x; acc[3][1] += r3 * uc.y; acc[3][2] += r3 * uc.z; acc[3][3] += r3 * uc.w;
    }

    float* go = out + base;
    #pragma unroll
    for (int i = 0; i < 4; ++i) {
        float4 v = make_float4(acc[i][0], acc[i][1], acc[i][2], acc[i][3]);
        *reinterpret_cast<float4*>(go + (4 * ta + i) * 64 + 4 * tb) = v;
    }
}

extern "C" void kernel_launch(void* const* d_in, const int* in_sizes, int n_in,
                              void* d_out, int out_size)
{
    const float* x = (const float*)d_in[0];
    float* out = (float*)d_out;
    int batches = in_sizes[0] / 4096;
    logm_jacobi_kernel<<<batches, 256>>>(x, out);
}

// round 6
// speedup vs baseline: 1.1230x; 1.1068x over previous
#include <cuda_runtime.h>

#define EPSV2    1e-8f         // EPSV^2
#define TOLSQ    1e-10f        // (1e-5)^2 relative orthogonality threshold
#define MAXSWEEP 30

// One CTA per 64x64 SPD matrix. One-sided Jacobi with REGISTER-RESIDENT
// columns. 32 teams (8 lanes each) own one pair-slot; columns live in
// registers (8 floats/lane/column). The circle tournament = fixed pairings
// + ring rotation of contents: intra-warp handoffs via shfl, warp-boundary
// handoffs via a small double-buffered shared staging area. LDS traffic per
// round drops ~7x vs the shared-resident version (R5 wall: L1=88%).
__global__ void __launch_bounds__(256, 4)
logm_jacobi_kernel(const float* __restrict__ in, float* __restrict__ out)
{
    // M: staging buffer during sweeps (first 2048 floats), U matrix for the
    // epilogue afterwards. wlog: log-eigenvalues.
    __shared__ __align__(16) float M[64 * 64];
    __shared__ float wlog[64];
    __shared__ int   s_flag;

    const int tid  = threadIdx.x;
    const int lane = tid & 31;
    const int warp = tid >> 5;
    const int team = lane >> 3;               // 4 teams per warp
    const int sl   = lane & 7;                // lane within team
    const unsigned tm = 0xffu << (team << 3); // team shfl mask
    const int k = warp * 4 + team;            // slot 0..31
    const bool slot0  = (k == 0);
    const bool slot31 = (k == 31);
    const size_t base = (size_t)blockIdx.x * 4096;

    // ---- load: slot k holds columns k (top) and 32+k (bottom) ----
    float T[8], B[8];
    {
        const float4* gt = reinterpret_cast<const float4*>(in + base + k * 64 + sl * 8);
        const float4* gb = reinterpret_cast<const float4*>(in + base + (32 + k) * 64 + sl * 8);
        float4 t0 = gt[0], t1 = gt[1], b0 = gb[0], b1 = gb[1];
        T[0]=t0.x; T[1]=t0.y; T[2]=t0.z; T[3]=t0.w;
        T[4]=t1.x; T[5]=t1.y; T[6]=t1.z; T[7]=t1.w;
        B[0]=b0.x; B[1]=b0.y; B[2]=b0.z; B[3]=b0.w;
        B[4]=b1.x; B[5]=b1.y; B[6]=b1.z; B[7]=b1.w;
    }

    // ---- one-sided Jacobi sweeps ----
    for (int sweep = 0; sweep < MAXSWEEP; ++sweep) {
        if (tid == 0) s_flag = 0;
        __syncthreads();

        for (int r = 0; r < 63; ++r) {
            // --- pair visit: all in registers ---
            float dpq = 0.f, dpp = 0.f, dqq = 0.f;
            #pragma unroll
            for (int i = 0; i < 8; ++i) {
                dpq = fmaf(T[i], B[i], dpq);
                dpp = fmaf(T[i], T[i], dpp);
                dqq = fmaf(B[i], B[i], dqq);
            }
            #pragma unroll
            for (int o = 4; o; o >>= 1) {
                dpq += __shfl_xor_sync(tm, dpq, o);
                dpp += __shfl_xor_sync(tm, dpp, o);
                dqq += __shfl_xor_sync(tm, dqq, o);
            }

            if (dpq * dpq > TOLSQ * dpp * dqq) {   // shfl-free branch body
                float tau = __fdividef(dqq - dpp, 2.0f * dpq);
                float t = copysignf(1.0f, tau) /
                          (fabsf(tau) + sqrtf(1.0f + tau * tau));
                float c = rsqrtf(1.0f + t * t);
                float s = t * c;
                #pragma unroll
                for (int i = 0; i < 8; ++i) {
                    float tp = c * T[i] - s * B[i];
                    B[i]     = s * T[i] + c * B[i];
                    T[i]     = tp;
                }
                if (sl == 0) s_flag = 1;
            }

            // --- ring exchange: T shifts +1 slot, B shifts -1 slot,
            //     slot0.top fixed, slot0.bot -> slot1.top, slot31.top -> slot31.bot ---
            const int par = r & 1;
            float* stT = M + par * 512;           // staged T for dest warp w
            float* stB = M + 1024 + par * 512;    // staged B for dest warp w
            if (team == 3 && warp < 7) {          // T crosses warp boundary ->
                float4* d = reinterpret_cast<float4*>(stT + (warp + 1) * 64 + sl * 8);
                d[0] = make_float4(T[0], T[1], T[2], T[3]);
                d[1] = make_float4(T[4], T[5], T[6], T[7]);
            }
            if (team == 0 && warp > 0) {          // B crosses warp boundary <-
                float4* d = reinterpret_cast<float4*>(stB + (warp - 1) * 64 + sl * 8);
                d[0] = make_float4(B[0], B[1], B[2], B[3]);
                d[1] = make_float4(B[4], B[5], B[6], B[7]);
            }
            __syncthreads();

            // unconditional shfls (all 32 lanes), predicated selects after
            #pragma unroll
            for (int i = 0; i < 8; ++i) {
                float contrib = slot0 ? B[i] : T[i];   // slot0 passes its B up
                float oldT = T[i];
                float u = __shfl_up_sync(0xffffffffu, contrib, 8);
                float d = __shfl_down_sync(0xffffffffu, B[i], 8);
                T[i] = slot0  ? oldT : u;              // slot0 top fixed
                B[i] = slot31 ? oldT : d;              // slot31: top -> bottom
            }
            if (team == 0 && warp > 0) {               // receive T from warp-1
                const float4* s4 = reinterpret_cast<const float4*>(stT + warp * 64 + sl * 8);
                float4 a = s4[0], b = s4[1];
                T[0]=a.x; T[1]=a.y; T[2]=a.z; T[3]=a.w;
                T[4]=b.x; T[5]=b.y; T[6]=b.z; T[7]=b.w;
            }
            if (team == 3 && warp < 7) {               // receive B from warp+1
                const float4* s4 = reinterpret_cast<const float4*>(stB + warp * 64 + sl * 8);
                float4 a = s4[0], b = s4[1];
                B[0]=a.x; B[1]=a.y; B[2]=a.z; B[3]=a.w;
                B[4]=b.x; B[5]=b.y; B[6]=b.z; B[7]=b.w;
            }
        }

        int active = s_flag;
        __syncthreads();          // everyone reads flag before next reset;
        if (!active) break;       // also fences last round's staging reads
    }

    // ---- norms -> eigenvalues; normalized columns -> M (order-free) ----
    {
        float dpp = 0.f, dqq = 0.f;
        #pragma unroll
        for (int i = 0; i < 8; ++i) {
            dpp = fmaf(T[i], T[i], dpp);
            dqq = fmaf(B[i], B[i], dqq);
        }
        #pragma unroll
        for (int o = 4; o; o >>= 1) {
            dpp += __shfl_xor_sync(tm, dpp, o);
            dqq += __shfl_xor_sync(tm, dqq, o);
        }
        float it = (dpp > 1e-30f) ? rsqrtf(dpp) : 0.0f;
        float ib = (dqq > 1e-30f) ? rsqrtf(dqq) : 0.0f;
        float4* mt = reinterpret_cast<float4*>(M + (2 * k) * 64 + sl * 8);
        float4* mb = reinterpret_cast<float4*>(M + (2 * k + 1) * 64 + sl * 8);
        mt[0] = make_float4(T[0]*it, T[1]*it, T[2]*it, T[3]*it);
        mt[1] = make_float4(T[4]*it, T[5]*it, T[6]*it, T[7]*it);
        mb[0] = make_float4(B[0]*ib, B[1]*ib, B[2]*ib, B[3]*ib);
        mb[1] = make_float4(B[4]*ib, B[5]*ib, B[6]*ib, B[7]*ib);
        if (sl == 0) {
            wlog[2 * k]     = 0.5f * logf(fmaxf(dpp, EPSV2));
            wlog[2 * k + 1] = 0.5f * logf(fmaxf(dqq, EPSV2));
        }
    }
    __syncthreads();

    // ---- O = U diag(w) U^T, 4x4 register tile per thread ----
    const int ta = tid >> 4;
    const int tb = tid & 15;
    float acc[4][4];
    #pragma unroll
    for (int i = 0; i < 4; ++i)
        #pragma unroll
        for (int j = 0; j < 4; ++j) acc[i][j] = 0.0f;

    for (int kk = 0; kk < 64; ++kk) {
        float w = wlog[kk];
        float4 ur = *reinterpret_cast<const float4*>(M + kk * 64 + 4 * ta);
        float4 uc = *reinterpret_cast<const float4*>(M + kk * 64 + 4 * tb);
        float r0 = w * ur.x, r1 = w * ur.y, r2 = w * ur.z, r3 = w * ur.w;
        acc[0][0] += r0 * uc.x; acc[0][1] += r0 * uc.y; acc[0][2] += r0 * uc.z; acc[0][3] += r0 * uc.w;
        acc[1][0] += r1 * uc.x; acc[1][1] += r1 * uc.y; acc[1][2] += r1 * uc.z; acc[1][3] += r1 * uc.w;
        acc[2][0] += r2 * uc.x; acc[2][1] += r2 * uc.y; acc[2][2] += r2 * uc.z; acc[2][3] += r2 * uc.w;
        acc[3][0] += r3 * uc.x; acc[3][1] += r3 * uc.y; acc[3][2] += r3 * uc.z; acc[3][3] += r3 * uc.w;
    }

    float* go = out + base;
    #pragma unroll
    for (int i = 0; i < 4; ++i) {
        float4 v = make_float4(acc[i][0], acc[i][1], acc[i][2], acc[i][3]);
        *reinterpret_cast<float4*>(go + (4 * ta + i) * 64 + 4 * tb) = v;
    }
}

extern "C" void kernel_launch(void* const* d_in, const int* in_sizes, int n_in,
                              void* d_out, int out_size)
{
    const float* x = (const float*)d_in[0];
    float* out = (float*)d_out;
    int batches = in_sizes[0] / 4096;
    logm_jacobi_kernel<<<batches, 256>>>(x, out);
}